// round 6
// baseline (speedup 1.0000x reference)
#include <cuda_runtime.h>
#include <cuda_bf16.h>

// Problem constants
#define TT    256
#define BB    1000
#define DD    300
#define H4    8
#define NCONS_BLK 16            // consumer blocks
#define DCH   20                // d-cols per chunk
#define NCH   15                // 15 * 20 = 300
#define CHUNK_F4 (BB * 5)       // 5000 float4 per chunk
#define SXF   (BB * DCH)        // 20000 floats per ring slot

// smem (floats): sW[2400] | sB[8] | cnt[2 ints @2408] | pad->2416 | ring[2][20000]
#define SW_FLOATS 2400
#define CNT_OFF   2408
#define SX_OFF    2416
#define SMEM_FLOATS (SX_OFF + 2 * SXF)
#define SMEM_BYTES  (SMEM_FLOATS * 4)    // 169,664 B

#define NPROD_THREADS 320   // 8 compute warps + 2 loader warps

__device__ float g_xg[TT * BB * H4];   // xg[t][b][g]  (8.192 MB)
__device__ int   g_flags[TT];

// ---------------- helpers ----------------
__device__ __forceinline__ void fma2(unsigned long long& acc,
                                     unsigned long long a,
                                     unsigned long long b) {
    asm volatile("fma.rn.f32x2 %0, %1, %2, %3;" : "=l"(acc) : "l"(a), "l"(b), "l"(acc));
}
__device__ __forceinline__ unsigned long long pack2(float x) {
    unsigned long long r;
    asm("mov.b64 %0, {%1, %1};" : "=l"(r) : "r"(__float_as_uint(x)));
    return r;
}
__device__ __forceinline__ void unpack2(unsigned long long p, float& lo, float& hi) {
    unsigned a, b;
    asm("mov.b64 {%0, %1}, %2;" : "=r"(a), "=r"(b) : "l"(p));
    lo = __uint_as_float(a);
    hi = __uint_as_float(b);
}

__device__ __forceinline__ void set_flag(int t) {
    asm volatile("st.release.gpu.global.u32 [%0], %1;" :: "l"(&g_flags[t]), "r"(1u) : "memory");
}
__device__ __forceinline__ void wait_flag(int t) {
    unsigned v;
    for (;;) {
        asm volatile("ld.acquire.gpu.global.u32 %0, [%1];"
                     : "=r"(v) : "l"(&g_flags[t]) : "memory");
        if (v) return;
        __nanosleep(32);
    }
}

// smem release add / acquire load on counters
__device__ __forceinline__ void smem_add_release(int* p, int v) {
    unsigned a = (unsigned)__cvta_generic_to_shared(p);
    asm volatile("red.release.cta.shared::cta.add.u32 [%0], %1;" :: "r"(a), "r"((unsigned)v) : "memory");
}
__device__ __forceinline__ int smem_ld_acquire(int* p) {
    unsigned a = (unsigned)__cvta_generic_to_shared(p);
    unsigned v;
    asm volatile("ld.acquire.cta.shared::cta.u32 %0, [%1];" : "=r"(v) : "r"(a) : "memory");
    return (int)v;
}

// fast overflow-safe activations (~1e-6 accurate)
__device__ __forceinline__ float sigf(float x) {
    x = fminf(fmaxf(x, -30.0f), 30.0f);
    return __fdividef(1.0f, 1.0f + __expf(-x));
}
__device__ __forceinline__ float tanh_(float x) {
    x = fminf(fmaxf(x, -15.0f), 15.0f);
    float e = __expf(-2.0f * x);
    return __fdividef(1.0f - e, 1.0f + e);
}

__global__ void reset_kernel() {
    g_flags[threadIdx.x] = 0;
}

__global__ __launch_bounds__(NPROD_THREADS, 1) void fused_kernel(
    const float* __restrict__ x,      // [T,B,300]
    const float* __restrict__ Wih0,   // [8,300]
    const float* __restrict__ bih0,
    const float* __restrict__ bhh0,
    const float* __restrict__ h0in,   // [2,B,2]
    const float* __restrict__ c0in,
    const float* __restrict__ Whh0,   // [8,2]
    const float* __restrict__ Wih1,   // [8,2]
    const float* __restrict__ Whh1,   // [8,2]
    const float* __restrict__ bih1,
    const float* __restrict__ bhh1,
    const float* __restrict__ Wlin,   // [1,2]
    const float* __restrict__ blin,
    float* __restrict__ out,          // [B]
    int nprod)
{
    extern __shared__ float smem[];
    const int bid = blockIdx.x;
    const int tid = threadIdx.x;

    if (bid < nprod) {
        // =================== PRODUCER (warp-specialized) ===================
        float* sW = smem;                  // sW[d*8+g] = Wih0[g*300+d]
        float* sB = smem + SW_FLOATS;
        int*  cnt = (int*)(smem + CNT_OFF);   // cnt[0]=ready, cnt[1]=done

        if (tid == 0) { cnt[0] = 0; cnt[1] = 0; }
        for (int i = tid; i < DD * H4; i += NPROD_THREADS) {
            int d = i >> 3, g = i & 7;
            sW[i] = Wih0[g * DD + d];
        }
        if (tid < H4) sB[tid] = bih0[tid] + bhh0[tid];
        __syncthreads();

        const int lane = tid & 31;

        if (tid >= 256) {
            // ---------------- LOADER warps (2) ----------------
            const int w = (tid - 256) >> 5;   // 0 or 1
            const float4* x4 = reinterpret_cast<const float4*>(x);
            float4* ring = reinterpret_cast<float4*>(smem + SX_OFF);

            int k = 0;
            for (int t = bid; t < TT; t += nprod) {
                const float4* tb = x4 + (long)t * (BB * 75);
                #pragma unroll 1
                for (int c = 0; c < NCH; c++, k++) {
                    if (k >= 2) {
                        if (lane == 0) {
                            while (smem_ld_acquire(&cnt[1]) < 8 * (k - 1)) { }
                        }
                        __syncwarp();
                    }
                    const float4* src = tb + c * 5;
                    float4* dst = ring + (k & 1) * (SXF / 4);
                    // this warp stages ops [w*2500, (w+1)*2500)
                    #pragma unroll 1
                    for (int s0 = 0; s0 < 2500; s0 += 256) {
                        float4 v[8];
                        int di[8];
                        bool ok[8];
                        #pragma unroll
                        for (int u = 0; u < 8; u++) {
                            int s = s0 + u * 32 + lane;
                            ok[u] = (s < 2500);
                            int o = w * 2500 + (ok[u] ? s : 0);
                            int r = o / 5;
                            int q = o - r * 5;
                            di[u] = r * 5 + q;
                            if (ok[u]) v[u] = src[(long)r * 75 + q];
                        }
                        #pragma unroll
                        for (int u = 0; u < 8; u++)
                            if (ok[u]) dst[di[u]] = v[u];
                    }
                    __syncwarp();
                    if (lane == 0) smem_add_release(&cnt[0], 1);
                }
            }
            return;
        }

        // ---------------- COMPUTE warps (8) ----------------
        ulonglong2 bias01 = *reinterpret_cast<const ulonglong2*>(&sB[0]);
        ulonglong2 bias23 = *reinterpret_cast<const ulonglong2*>(&sB[4]);
        const ulonglong2* wpb = reinterpret_cast<const ulonglong2*>(sW);

        int k = 0;
        #pragma unroll 1
        for (int t = bid; t < TT; t += nprod) {
            unsigned long long acc[4][4];
            #pragma unroll
            for (int kk = 0; kk < 4; kk++) {
                acc[kk][0] = bias01.x; acc[kk][1] = bias01.y;
                acc[kk][2] = bias23.x; acc[kk][3] = bias23.y;
            }

            #pragma unroll 1
            for (int c = 0; c < NCH; c++, k++) {
                if (lane == 0) {
                    while (smem_ld_acquire(&cnt[0]) < 2 * (k + 1)) { }
                }
                __syncwarp();

                if (tid < 250) {
                    const float* sx = smem + SX_OFF + (k & 1) * SXF;
                    const float4* xr0 = reinterpret_cast<const float4*>(sx + (tid      ) * DCH);
                    const float4* xr1 = reinterpret_cast<const float4*>(sx + (tid + 250) * DCH);
                    const float4* xr2 = reinterpret_cast<const float4*>(sx + (tid + 500) * DCH);
                    const float4* xr3 = reinterpret_cast<const float4*>(sx + (tid + 750) * DCH);
                    const ulonglong2* wp = wpb + c * (DCH * 2);
                    #pragma unroll
                    for (int dq = 0; dq < DCH / 4; dq++) {
                        float4 xv[4];
                        xv[0] = xr0[dq]; xv[1] = xr1[dq];
                        xv[2] = xr2[dq]; xv[3] = xr3[dq];
                        #pragma unroll
                        for (int j = 0; j < 4; j++) {
                            ulonglong2 wA = wp[(dq * 4 + j) * 2];
                            ulonglong2 wB = wp[(dq * 4 + j) * 2 + 1];
                            const float xs0 = (j == 0) ? xv[0].x : (j == 1) ? xv[0].y : (j == 2) ? xv[0].z : xv[0].w;
                            const float xs1 = (j == 0) ? xv[1].x : (j == 1) ? xv[1].y : (j == 2) ? xv[1].z : xv[1].w;
                            const float xs2 = (j == 0) ? xv[2].x : (j == 1) ? xv[2].y : (j == 2) ? xv[2].z : xv[2].w;
                            const float xs3 = (j == 0) ? xv[3].x : (j == 1) ? xv[3].y : (j == 2) ? xv[3].z : xv[3].w;
                            unsigned long long p0 = pack2(xs0), p1 = pack2(xs1);
                            unsigned long long p2 = pack2(xs2), p3 = pack2(xs3);
                            fma2(acc[0][0], p0, wA.x); fma2(acc[0][1], p0, wA.y);
                            fma2(acc[0][2], p0, wB.x); fma2(acc[0][3], p0, wB.y);
                            fma2(acc[1][0], p1, wA.x); fma2(acc[1][1], p1, wA.y);
                            fma2(acc[1][2], p1, wB.x); fma2(acc[1][3], p1, wB.y);
                            fma2(acc[2][0], p2, wA.x); fma2(acc[2][1], p2, wA.y);
                            fma2(acc[2][2], p2, wB.x); fma2(acc[2][3], p2, wB.y);
                            fma2(acc[3][0], p3, wA.x); fma2(acc[3][1], p3, wA.y);
                            fma2(acc[3][2], p3, wB.x); fma2(acc[3][3], p3, wB.y);
                        }
                    }
                }
                // all lanes reached here => their LDS data consumed (fma issue needs it)
                __syncwarp();
                if (lane == 0) smem_add_release(&cnt[1], 1);
            }

            // ---- writeback + publish ----
            if (tid < 250) {
                #pragma unroll
                for (int kk = 0; kk < 4; kk++) {
                    const int row = t * BB + tid + kk * 250;
                    float4 o0, o1;
                    unpack2(acc[kk][0], o0.x, o0.y);
                    unpack2(acc[kk][1], o0.z, o0.w);
                    unpack2(acc[kk][2], o1.x, o1.y);
                    unpack2(acc[kk][3], o1.z, o1.w);
                    float4* dst = reinterpret_cast<float4*>(&g_xg[(size_t)row * H4]);
                    dst[0] = o0;
                    dst[1] = o1;
                }
            }
            asm volatile("bar.sync 1, 256;" ::: "memory");   // compute warps only
            if (tid == 0) {
                __threadfence();
                set_flag(t);
            }
        }
        return;
    }

    // =================== CONSUMER ===================
    // 16 blocks x 4 warps (threads 0..127). Lanes 0-15: layer0 of 16 elements,
    // lanes 16-31: layer1 of the same elements, lagged one timestep.
    if (tid >= 128) return;
    const int warp = tid >> 5;
    const int lane = tid & 31;
    const bool l1  = (lane >= 16);
    const int e    = ((bid - nprod) * 4 + warp) * 16 + (lane & 15);
    const int b    = (e < BB) ? e : (BB - 1);

    float A0[H4], A1[H4], C0[H4], C1[H4], vb[H4];
    float ha, hb, ca, cb;
    float hpa = 0.0f, hpb = 0.0f;

    if (!l1) {
        #pragma unroll
        for (int g = 0; g < H4; g++) {
            A0[g] = __ldg(&Whh0[g * 2 + 0]);
            A1[g] = __ldg(&Whh0[g * 2 + 1]);
            C0[g] = 0.0f; C1[g] = 0.0f; vb[g] = 0.0f;
        }
        ha = h0in[b * 2 + 0]; hb = h0in[b * 2 + 1];
        ca = c0in[b * 2 + 0]; cb = c0in[b * 2 + 1];
    } else {
        #pragma unroll
        for (int g = 0; g < H4; g++) {
            A0[g] = __ldg(&Whh1[g * 2 + 0]);
            A1[g] = __ldg(&Whh1[g * 2 + 1]);
            C0[g] = __ldg(&Wih1[g * 2 + 0]);
            C1[g] = __ldg(&Wih1[g * 2 + 1]);
            vb[g] = __ldg(&bih1[g]) + __ldg(&bhh1[g]);
        }
        ha = h0in[BB * 2 + b * 2 + 0]; hb = h0in[BB * 2 + b * 2 + 1];
        ca = c0in[BB * 2 + b * 2 + 0]; cb = c0in[BB * 2 + b * 2 + 1];
    }
    const float wl0 = __ldg(&Wlin[0]), wl1 = __ldg(&Wlin[1]), bl = __ldg(&blin[0]);

    const float4* xg4 = reinterpret_cast<const float4*>(g_xg);
    const int idx0 = b * 2;

    wait_flag(0);
    if (!l1) {
        float4 v0 = xg4[idx0];
        float4 v1 = xg4[idx0 + 1];
        vb[0] = v0.x; vb[1] = v0.y; vb[2] = v0.z; vb[3] = v0.w;
        vb[4] = v1.x; vb[5] = v1.y; vb[6] = v1.z; vb[7] = v1.w;
    }

    for (int s = 0; s <= TT; s++) {
        float4 n0, n1;
        const bool pf = (s + 1 < TT);
        if (pf) {
            wait_flag(s + 1);
            if (!l1) {
                n0 = xg4[idx0 + (s + 1) * (BB * 2)];
                n1 = xg4[idx0 + (s + 1) * (BB * 2) + 1];
            }
        }

        float pre[H4];
        #pragma unroll
        for (int g = 0; g < H4; g++)
            pre[g] = fmaf(C0[g], hpa, fmaf(C1[g], hpb, vb[g]));
        #pragma unroll
        for (int g = 0; g < H4; g++)
            pre[g] = fmaf(A0[g], ha, fmaf(A1[g], hb, pre[g]));

        float i0 = sigf(pre[0]),  i1 = sigf(pre[1]);
        float f0 = sigf(pre[2]),  f1 = sigf(pre[3]);
        float g0 = tanh_(pre[4]), g1 = tanh_(pre[5]);
        float o0 = sigf(pre[6]),  o1 = sigf(pre[7]);
        float nca = fmaf(f0, ca, i0 * g0);
        float ncb = fmaf(f1, cb, i1 * g1);
        float nha = o0 * tanh_(nca);
        float nhb = o1 * tanh_(ncb);

        const bool valid = l1 ? (s >= 1) : (s < TT);
        if (valid) { ca = nca; cb = ncb; ha = nha; hb = nhb; }

        hpa = __shfl_up_sync(0xffffffffu, ha, 16);
        hpb = __shfl_up_sync(0xffffffffu, hb, 16);

        if (pf && !l1) {
            vb[0] = n0.x; vb[1] = n0.y; vb[2] = n0.z; vb[3] = n0.w;
            vb[4] = n1.x; vb[5] = n1.y; vb[6] = n1.z; vb[7] = n1.w;
        }
    }

    if (l1 && e < BB)
        out[b] = fmaf(wl0, ha, fmaf(wl1, hb, bl));
}

// ---------------------------------------------------------------------------
extern "C" void kernel_launch(void* const* d_in, const int* in_sizes, int n_in,
                              void* d_out, int out_size)
{
    const float* x     = (const float*)d_in[0];
    const float* h0    = (const float*)d_in[1];
    const float* c0    = (const float*)d_in[2];
    const float* Wih0  = (const float*)d_in[3];
    const float* Whh0  = (const float*)d_in[4];
    const float* bih0  = (const float*)d_in[5];
    const float* bhh0  = (const float*)d_in[6];
    const float* Wih1  = (const float*)d_in[7];
    const float* Whh1  = (const float*)d_in[8];
    const float* bih1  = (const float*)d_in[9];
    const float* bhh1  = (const float*)d_in[10];
    const float* Wlin  = (const float*)d_in[11];
    const float* blin  = (const float*)d_in[12];
    float* out = (float*)d_out;

    int dev = 0, nsm = 148;
    cudaGetDevice(&dev);
    cudaDeviceGetAttribute(&nsm, cudaDevAttrMultiProcessorCount, dev);
    if (nsm < NCONS_BLK + 8) nsm = NCONS_BLK + 8;
    int nprod = nsm - NCONS_BLK;
    if (nprod > TT) nprod = TT;

    cudaFuncSetAttribute(fused_kernel, cudaFuncAttributeMaxDynamicSharedMemorySize, SMEM_BYTES);

    reset_kernel<<<1, TT>>>();
    fused_kernel<<<nprod + NCONS_BLK, NPROD_THREADS, SMEM_BYTES>>>(
        x, Wih0, bih0, bhh0,
        h0, c0, Whh0, Wih1, Whh1, bih1, bhh1, Wlin, blin,
        out, nprod);
}

// round 7
// speedup vs baseline: 2.2962x; 2.2962x over previous
#include <cuda_runtime.h>
#include <cuda_bf16.h>

// Problem constants
#define TT    256
#define BB    1000
#define DD    300
#define H4    8
#define NCONS 8                 // consumer blocks (first 8 of grid)
#define NPROD (TT * 4)          // 1024 producer blocks, one per (t, quarter)

__device__ float g_xg[TT * BB * H4];   // xg[t][b][g]  (8.192 MB)
__device__ int   g_cnt[TT];            // quarters completed per timestep

// ---------------- helpers ----------------
__device__ __forceinline__ void fma2(unsigned long long& acc,
                                     unsigned long long a,
                                     unsigned long long b) {
    asm volatile("fma.rn.f32x2 %0, %1, %2, %3;" : "=l"(acc) : "l"(a), "l"(b), "l"(acc));
}
__device__ __forceinline__ unsigned long long pack2(float x) {
    unsigned long long r;
    asm("mov.b64 %0, {%1, %1};" : "=l"(r) : "r"(__float_as_uint(x)));
    return r;
}
__device__ __forceinline__ void unpack2(unsigned long long p, float& lo, float& hi) {
    unsigned a, b;
    asm("mov.b64 {%0, %1}, %2;" : "=r"(a), "=r"(b) : "l"(p));
    lo = __uint_as_float(a);
    hi = __uint_as_float(b);
}

__device__ __forceinline__ int ld_acquire(const int* p) {
    unsigned v;
    asm volatile("ld.acquire.gpu.global.u32 %0, [%1];" : "=r"(v) : "l"(p) : "memory");
    return (int)v;
}
__device__ __forceinline__ void wait_cnt(int t) {
    if (ld_acquire(&g_cnt[t]) >= 4) return;
    for (;;) {
        if (ld_acquire(&g_cnt[t]) >= 4) return;
        __nanosleep(64);
    }
}

// fast overflow-safe activations (~1e-6 accurate)
__device__ __forceinline__ float sigf(float x) {
    x = fminf(fmaxf(x, -30.0f), 30.0f);
    return __fdividef(1.0f, 1.0f + __expf(-x));
}
__device__ __forceinline__ float tanh_(float x) {
    x = fminf(fmaxf(x, -15.0f), 15.0f);
    float e = __expf(-2.0f * x);
    return __fdividef(1.0f - e, 1.0f + e);
}

__global__ void reset_kernel() {
    g_cnt[threadIdx.x] = 0;
}

__global__ __launch_bounds__(256, 2) void fused_kernel(
    const float* __restrict__ x,      // [T,B,300]
    const float* __restrict__ Wih0,   // [8,300]
    const float* __restrict__ bih0,
    const float* __restrict__ bhh0,
    const float* __restrict__ h0in,   // [2,B,2]
    const float* __restrict__ c0in,
    const float* __restrict__ Whh0,   // [8,2]
    const float* __restrict__ Wih1,   // [8,2]
    const float* __restrict__ Whh1,   // [8,2]
    const float* __restrict__ bih1,
    const float* __restrict__ bhh1,
    const float* __restrict__ Wlin,   // [1,2]
    const float* __restrict__ blin,
    float* __restrict__ out)          // [B]
{
    __shared__ float sW[DD * H4];     // sW[d*8+g] = Wih0[g*300+d]
    __shared__ float sB[H4];

    const int bid = blockIdx.x;
    const int tid = threadIdx.x;

    if (bid >= NCONS) {
        // =================== PRODUCER (one block per (t, quarter)) ===========
        const int pid = bid - NCONS;
        const int t   = pid >> 2;
        const int q   = pid & 3;

        for (int i = tid; i < DD * H4; i += 256) {
            int d = i >> 3, g = i & 7;
            sW[i] = Wih0[g * DD + d];
        }
        if (tid < H4) sB[tid] = bih0[tid] + bhh0[tid];
        __syncthreads();

        if (tid < 250) {
            const int row = t * BB + q * 250 + tid;
            const float4* xrow = reinterpret_cast<const float4*>(x + (size_t)row * DD);
            const ulonglong2* wp = reinterpret_cast<const ulonglong2*>(sW);

            ulonglong2 b01 = *reinterpret_cast<const ulonglong2*>(&sB[0]);
            ulonglong2 b23 = *reinterpret_cast<const ulonglong2*>(&sB[4]);
            unsigned long long a0 = b01.x, a1 = b01.y, a2 = b23.x, a3 = b23.y;

            #pragma unroll 5
            for (int d4 = 0; d4 < DD / 4; d4++) {
                float4 v = xrow[d4];
                #pragma unroll
                for (int j = 0; j < 4; j++) {
                    const float xs = (j == 0) ? v.x : (j == 1) ? v.y : (j == 2) ? v.z : v.w;
                    unsigned long long xp = pack2(xs);
                    ulonglong2 wA = wp[(d4 * 4 + j) * 2];
                    ulonglong2 wB = wp[(d4 * 4 + j) * 2 + 1];
                    fma2(a0, xp, wA.x);
                    fma2(a1, xp, wA.y);
                    fma2(a2, xp, wB.x);
                    fma2(a3, xp, wB.y);
                }
            }

            float4 o0, o1;
            unpack2(a0, o0.x, o0.y);
            unpack2(a1, o0.z, o0.w);
            unpack2(a2, o1.x, o1.y);
            unpack2(a3, o1.z, o1.w);
            float4* dst = reinterpret_cast<float4*>(&g_xg[(size_t)row * H4]);
            dst[0] = o0;
            dst[1] = o1;
        }
        __threadfence();
        __syncthreads();
        if (tid == 0) atomicAdd(&g_cnt[t], 1);
        return;
    }

    // =================== CONSUMER (blocks 0..7, 8 warps each) ================
    // Lanes 0-15: layer0 of 16 elements, lanes 16-31: layer1, lagged one step.
    const int warp = tid >> 5;
    const int lane = tid & 31;
    const bool l1  = (lane >= 16);
    const int e    = (bid * 8 + warp) * 16 + (lane & 15);   // 0..1023
    const int b    = (e < BB) ? e : (BB - 1);

    float A0[H4], A1[H4], C0[H4], C1[H4], vb[H4];
    float ha, hb, ca, cb;
    float hpa = 0.0f, hpb = 0.0f;

    if (!l1) {
        #pragma unroll
        for (int g = 0; g < H4; g++) {
            A0[g] = __ldg(&Whh0[g * 2 + 0]);
            A1[g] = __ldg(&Whh0[g * 2 + 1]);
            C0[g] = 0.0f; C1[g] = 0.0f; vb[g] = 0.0f;
        }
        ha = h0in[b * 2 + 0]; hb = h0in[b * 2 + 1];
        ca = c0in[b * 2 + 0]; cb = c0in[b * 2 + 1];
    } else {
        #pragma unroll
        for (int g = 0; g < H4; g++) {
            A0[g] = __ldg(&Whh1[g * 2 + 0]);
            A1[g] = __ldg(&Whh1[g * 2 + 1]);
            C0[g] = __ldg(&Wih1[g * 2 + 0]);
            C1[g] = __ldg(&Wih1[g * 2 + 1]);
            vb[g] = __ldg(&bih1[g]) + __ldg(&bhh1[g]);
        }
        ha = h0in[BB * 2 + b * 2 + 0]; hb = h0in[BB * 2 + b * 2 + 1];
        ca = c0in[BB * 2 + b * 2 + 0]; cb = c0in[BB * 2 + b * 2 + 1];
    }
    const float wl0 = __ldg(&Wlin[0]), wl1 = __ldg(&Wlin[1]), bl = __ldg(&blin[0]);

    const float4* xg4 = reinterpret_cast<const float4*>(g_xg);
    const int idx0 = b * 2;

    wait_cnt(0);
    if (!l1) {
        float4 v0 = xg4[idx0];
        float4 v1 = xg4[idx0 + 1];
        vb[0] = v0.x; vb[1] = v0.y; vb[2] = v0.z; vb[3] = v0.w;
        vb[4] = v1.x; vb[5] = v1.y; vb[6] = v1.z; vb[7] = v1.w;
    }

    for (int s = 0; s <= TT; s++) {
        float4 n0, n1;
        const bool pf = (s + 1 < TT);
        if (pf) {
            wait_cnt(s + 1);
            if (!l1) {
                n0 = xg4[idx0 + (s + 1) * (BB * 2)];
                n1 = xg4[idx0 + (s + 1) * (BB * 2) + 1];
            }
        }

        float pre[H4];
        #pragma unroll
        for (int g = 0; g < H4; g++)
            pre[g] = fmaf(C0[g], hpa, fmaf(C1[g], hpb, vb[g]));
        #pragma unroll
        for (int g = 0; g < H4; g++)
            pre[g] = fmaf(A0[g], ha, fmaf(A1[g], hb, pre[g]));

        float i0 = sigf(pre[0]),  i1 = sigf(pre[1]);
        float f0 = sigf(pre[2]),  f1 = sigf(pre[3]);
        float g0 = tanh_(pre[4]), g1 = tanh_(pre[5]);
        float o0 = sigf(pre[6]),  o1 = sigf(pre[7]);
        float nca = fmaf(f0, ca, i0 * g0);
        float ncb = fmaf(f1, cb, i1 * g1);
        float nha = o0 * tanh_(nca);
        float nhb = o1 * tanh_(ncb);

        const bool valid = l1 ? (s >= 1) : (s < TT);
        if (valid) { ca = nca; cb = ncb; ha = nha; hb = nhb; }

        hpa = __shfl_up_sync(0xffffffffu, ha, 16);
        hpb = __shfl_up_sync(0xffffffffu, hb, 16);

        if (pf && !l1) {
            vb[0] = n0.x; vb[1] = n0.y; vb[2] = n0.z; vb[3] = n0.w;
            vb[4] = n1.x; vb[5] = n1.y; vb[6] = n1.z; vb[7] = n1.w;
        }
    }

    if (l1 && e < BB)
        out[b] = fmaf(wl0, ha, fmaf(wl1, hb, bl));
}

// ---------------------------------------------------------------------------
extern "C" void kernel_launch(void* const* d_in, const int* in_sizes, int n_in,
                              void* d_out, int out_size)
{
    const float* x     = (const float*)d_in[0];
    const float* h0    = (const float*)d_in[1];
    const float* c0    = (const float*)d_in[2];
    const float* Wih0  = (const float*)d_in[3];
    const float* Whh0  = (const float*)d_in[4];
    const float* bih0  = (const float*)d_in[5];
    const float* bhh0  = (const float*)d_in[6];
    const float* Wih1  = (const float*)d_in[7];
    const float* Whh1  = (const float*)d_in[8];
    const float* bih1  = (const float*)d_in[9];
    const float* bhh1  = (const float*)d_in[10];
    const float* Wlin  = (const float*)d_in[11];
    const float* blin  = (const float*)d_in[12];
    float* out = (float*)d_out;

    reset_kernel<<<1, TT>>>();
    fused_kernel<<<NCONS + NPROD, 256>>>(
        x, Wih0, bih0, bhh0,
        h0, c0, Whh0, Wih1, Whh1, bih1, bhh1, Wlin, blin,
        out);
}